// round 13
// baseline (speedup 1.0000x reference)
#include <cuda_runtime.h>

// HEALPix padding: data [B*12, 256, 64, 64] f32, p=2 -> out [B*12, 256, 68, 68].
//
// One block per (batch, face, channel-PAIR). The block stages TWO 64x64 face
// planes (consecutive channels) in shared memory, then emits both 68x68
// output planes as float4 quads, computing the spatial mapping (i, jq, table
// entries) ONCE per quad and applying it to both channels. Interior quads
// read two aligned float4s from smem and recombine across the 2-column
// shift; edge quads / border rows use a uint16 gather table
// (face<<12 | offset) with blended _tl/_br diagonals fixed up inline.

#define HH 64
#define P  2
#define PH 68
#define PW 68
#define NPLANE (PH*PW)        // 4624
#define NQPP   (NPLANE/4)     // 1156
#define NC  256
#define NFACE 12
#define NTAB (NFACE*NPLANE)

__device__ unsigned short g_tab16[NTAB];

__device__ __forceinline__ int idx64(int r, int c) { return r * HH + c; }

__global__ void build_table_kernel() {
    int t = blockIdx.x * blockDim.x + threadIdx.x;
    if (t >= NTAB) return;
    int f   = t / NPLANE;
    int rem = t - f * NPLANE;
    int i   = rem / PW;
    int j   = rem - i * PW;

    int ii = i - P;
    int jj = j - P;
    int rb = i - P - HH;
    int jr = j - P - HH;

    int f1 = 0, o1 = 0;

    if (f < 4) {
        // north faces: _pn
        int n   = f;
        int Ft  = (n + 1) & 3;
        int Ftl = (n + 2) & 3;
        int Fl  = (n + 3) & 3;
        int Fbl = (n + 3) & 3;
        int Fb  = n + 4;
        int Fbr = n + 8;
        int Fr  = 4 + ((n + 1) & 3);
        int Ftr = (n + 1) & 3;
        if (i < P) {
            if (j < P)            { f1 = Ftl; o1 = idx64(P-1-i, P-1-j); }
            else if (j < P + HH)  { f1 = Ft;  o1 = idx64(jj, P-1-i); }
            else                  { f1 = Ftr; o1 = idx64(HH-P+i, jr); }
        } else if (i < P + HH) {
            if (j < P)            { f1 = Fl;  o1 = idx64(P-1-j, ii); }
            else if (j < P + HH)  { f1 = n;   o1 = idx64(ii, jj); }
            else                  { f1 = Fr;  o1 = idx64(ii, jr); }
        } else {
            if (j < P)            { f1 = Fbl; o1 = idx64(rb, HH-P+j); }
            else if (j < P + HH)  { f1 = Fb;  o1 = idx64(rb, jj); }
            else                  { f1 = Fbr; o1 = idx64(rb, jr); }
        }
    } else if (f < 8) {
        // equator faces: _pe (blend diagonals store src1; pad blends inline)
        int k   = f - 4;
        int Ft  = k;
        int Fl  = (k + 3) & 3;
        int Fbl = 4 + ((k + 3) & 3);
        int Fb  = 8 + ((k + 3) & 3);
        int Fr  = 8 + k;
        int Ftr = 4 + ((k + 1) & 3);
        if (i < P) {
            if (j < P) {
                if (i == j)       { f1 = Ft; o1 = idx64(HH-P+i, 0); }
                else if (j > i)   { f1 = Ft; o1 = idx64(HH-P+i, j-i-1); }
                else              { f1 = Fl; o1 = idx64(i-j-1, HH-P+j); }
            }
            else if (j < P + HH)  { f1 = Ft;  o1 = idx64(HH-P+i, jj); }
            else                  { f1 = Ftr; o1 = idx64(HH-P+i, jr); }
        } else if (i < P + HH) {
            if (j < P)            { f1 = Fl;  o1 = idx64(ii, HH-P+j); }
            else if (j < P + HH)  { f1 = f;   o1 = idx64(ii, jj); }
            else                  { f1 = Fr;  o1 = idx64(ii, jr); }
        } else {
            if (j < P)            { f1 = Fbl; o1 = idx64(rb, HH-P+j); }
            else if (j < P + HH)  { f1 = Fb;  o1 = idx64(rb, jj); }
            else {
                if (rb == jr)     { f1 = Fb; o1 = idx64(rb, HH-1); }
                else if (jr < rb) { f1 = Fb; o1 = idx64(rb, HH-rb+jr); }
                else              { f1 = Fr; o1 = idx64(HH-jr+rb, jr); }
            }
        }
    } else {
        // south faces: _ps
        int m   = f - 8;
        int Ft  = 4 + ((m + 1) & 3);
        int Ftl = m;
        int Fl  = 4 + m;
        int Fbl = 8 + ((m + 3) & 3);
        int Fb  = 8 + ((m + 3) & 3);
        int Fbr = 8 + ((m + 2) & 3);
        int Fr  = 8 + ((m + 1) & 3);
        int Ftr = 8 + ((m + 1) & 3);
        if (i < P) {
            if (j < P)            { f1 = Ftl; o1 = idx64(HH-P+i, HH-P+j); }
            else if (j < P + HH)  { f1 = Ft;  o1 = idx64(HH-P+i, jj); }
            else                  { f1 = Ftr; o1 = idx64(HH-P+i, jr); }
        } else if (i < P + HH) {
            if (j < P)            { f1 = Fl;  o1 = idx64(ii, HH-P+j); }
            else if (j < P + HH)  { f1 = f;   o1 = idx64(ii, jj); }
            else                  { f1 = Fr;  o1 = idx64(HH-1-jr, ii); }
        } else {
            if (j < P)            { f1 = Fbl; o1 = idx64(rb, HH-P+j); }
            else if (j < P + HH)  { f1 = Fb;  o1 = idx64(jj, HH-1-rb); }
            else                  { f1 = Fbr; o1 = idx64(HH-1-rb, HH-1-jr); }
        }
    }

    g_tab16[t] = (unsigned short)((f1 << 12) | o1);
}

__global__ __launch_bounds__(256)
void pad_kernel(const float* __restrict__ in, float* __restrict__ out) {
    __shared__ float4 s4[2 * HH * HH / 4];   // 32 KB: two face planes

    int rest  = blockIdx.x;                  // bf*128 + chPair
    int cpair = rest & 127;
    int bf    = rest >> 7;
    int b     = bf / NFACE;
    int fo    = bf - b * NFACE;
    int ch0   = cpair * 2;

    int sbase0 = ((b * NFACE) << 20) | (ch0 << 12);
    int sbase1 = sbase0 + 4096;              // ch0+1

    // Phase 1: stage both face planes, fully coalesced.
    {
        const float4* p0 = reinterpret_cast<const float4*>(in + sbase0 + (fo << 20));
        const float4* p1 = reinterpret_cast<const float4*>(in + sbase1 + (fo << 20));
        #pragma unroll
        for (int t = threadIdx.x; t < (HH * HH / 4); t += 256) {
            s4[t]        = __ldg(p0 + t);
            s4[1024 + t] = __ldg(p1 + t);
        }
    }
    __syncthreads();

    float4* out0 = reinterpret_cast<float4*>(out) + ((size_t)bf * NC + ch0) * NQPP;
    float4* out1 = out0 + NQPP;              // next channel = next plane
    const unsigned short* tab = &g_tab16[fo * NPLANE];

    bool eq = (unsigned)(fo - 4) < 4;        // equator face (has blends)
    int  k  = fo - 4;

    // Phase 2: emit 1156 quads for both channels.
    for (int q = threadIdx.x; q < NQPP; q += 256) {
        int i  = q / 17;                     // output row 0..67
        int jq = q - i * 17;                 // quad-in-row 0..16

        float4 v0, v1;
        if ((unsigned)(i - P) < HH) {
            int base = (i - P) * 16;
            if ((unsigned)(jq - 1) < 15u) {
                float4 A0 = s4[base + jq - 1],        B0 = s4[base + jq];
                float4 A1 = s4[1024 + base + jq - 1], B1 = s4[1024 + base + jq];
                v0 = make_float4(A0.z, A0.w, B0.x, B0.y);
                v1 = make_float4(A1.z, A1.w, B1.x, B1.y);
            } else if (jq == 0) {
                ushort2 e = *reinterpret_cast<const ushort2*>(&tab[q * 4]);
                int o0 = ((e.x >> 12) << 20) + (e.x & 4095);
                int o1 = ((e.y >> 12) << 20) + (e.y & 4095);
                float4 B0 = s4[base], B1 = s4[1024 + base];
                v0.x = __ldg(in + sbase0 + o0);  v0.y = __ldg(in + sbase0 + o1);
                v1.x = __ldg(in + sbase1 + o0);  v1.y = __ldg(in + sbase1 + o1);
                v0.z = B0.x; v0.w = B0.y;
                v1.z = B1.x; v1.w = B1.y;
            } else {                         // jq == 16
                ushort2 e = *reinterpret_cast<const ushort2*>(&tab[q * 4 + 2]);
                int o0 = ((e.x >> 12) << 20) + (e.x & 4095);
                int o1 = ((e.y >> 12) << 20) + (e.y & 4095);
                float4 A0 = s4[base + 15], A1 = s4[1024 + base + 15];
                v0.x = A0.z; v0.y = A0.w;
                v1.x = A1.z; v1.y = A1.w;
                v0.z = __ldg(in + sbase0 + o0);  v0.w = __ldg(in + sbase0 + o1);
                v1.z = __ldg(in + sbase1 + o0);  v1.w = __ldg(in + sbase1 + o1);
            }
        } else {
            // border rows (i in {0,1,66,67}): full table gather
            ushort4 e = *reinterpret_cast<const ushort4*>(&tab[q * 4]);
            int o0 = ((e.x >> 12) << 20) + (e.x & 4095);
            int o1 = ((e.y >> 12) << 20) + (e.y & 4095);
            int o2 = ((e.z >> 12) << 20) + (e.z & 4095);
            int o3 = ((e.w >> 12) << 20) + (e.w & 4095);
            v0.x = __ldg(in + sbase0 + o0);  v0.y = __ldg(in + sbase0 + o1);
            v0.z = __ldg(in + sbase0 + o2);  v0.w = __ldg(in + sbase0 + o3);
            v1.x = __ldg(in + sbase1 + o0);  v1.y = __ldg(in + sbase1 + o1);
            v1.z = __ldg(in + sbase1 + o2);  v1.w = __ldg(in + sbase1 + o3);

            // blended _tl/_br diagonal positions: equator faces only
            if (eq) {
                int pa = -1, pb = -1;
                if (q == 0)         { pa = (k << 20)             + idx64(HH-P, 0);
                                      pb = (((k+3)&3) << 20)     + idx64(0, HH-P); }
                else if (q == 17)   { pa = (k << 20)             + idx64(HH-1, 0);
                                      pb = (((k+3)&3) << 20)     + idx64(0, HH-1); }
                else if (q == 1138) { pa = ((8+((k+3)&3)) << 20) + idx64(0, HH-1);
                                      pb = ((8+k) << 20)         + idx64(HH-1, 0); }
                else if (q == 1155) { pa = ((8+((k+3)&3)) << 20) + idx64(1, HH-1);
                                      pb = ((8+k) << 20)         + idx64(HH-1, 1); }
                if (pa >= 0) {
                    float w0 = 0.5f * (__ldg(in + sbase0 + pa) + __ldg(in + sbase0 + pb));
                    float w1 = 0.5f * (__ldg(in + sbase1 + pa) + __ldg(in + sbase1 + pb));
                    if (q == 0)         { v0.x = w0; v1.x = w1; }
                    else if (q == 17)   { v0.y = w0; v1.y = w1; }
                    else if (q == 1138) { v0.z = w0; v1.z = w1; }
                    else                { v0.w = w0; v1.w = w1; }
                }
            }
        }

        __stcs(out0 + q, v0);
        __stcs(out1 + q, v1);
    }
}

extern "C" void kernel_launch(void* const* d_in, const int* in_sizes, int n_in,
                              void* d_out, int out_size) {
    const float* in = (const float*)d_in[0];
    float* out = (float*)d_out;

    build_table_kernel<<<(NTAB + 255) / 256, 256>>>();

    int nblocks = out_size / (NPLANE * 2);     // 96*256/2 = 12288 blocks
    pad_kernel<<<nblocks, 256>>>(in, out);
}

// round 15
// speedup vs baseline: 1.1671x; 1.1671x over previous
#include <cuda_runtime.h>

// HEALPix padding: data [B*12, 256, 64, 64] f32, p=2 -> out [B*12, 256, 68, 68].
//
// One block per (batch, face, channel) plane (R9 shape: 16KB smem, occ ~86%).
// Phase 1 stages the own 64x64 face into smem (coalesced float4).
// Phase 2 is split into two CONVERGENT loops:
//   Loop B (before __syncthreads): the 196 irregular quads (border rows i in
//     {0,1,66,67} plus jq==0 / jq==16 edge quads of center rows), all served
//     from global memory via the uint16 gather table (face<<12 | offset),
//     with the blended _tl/_br diagonals fixed up inline. Runs while the
//     smem fill drains, overlapping its scattered-gather latency.
//   Loop A (after sync): the 960 interior quads, branch-free: two aligned
//     LDS.128 + register recombine across the 2-column shift + one STG.128.

#define HH 64
#define P  2
#define PH 68
#define PW 68
#define NPLANE (PH*PW)        // 4624
#define NQPP   (NPLANE/4)     // 1156
#define NC  256
#define NFACE 12
#define NTAB (NFACE*NPLANE)

__device__ unsigned short g_tab16[NTAB];

__device__ __forceinline__ int idx64(int r, int c) { return r * HH + c; }

__global__ void build_table_kernel() {
    int t = blockIdx.x * blockDim.x + threadIdx.x;
    if (t >= NTAB) return;
    int f   = t / NPLANE;
    int rem = t - f * NPLANE;
    int i   = rem / PW;
    int j   = rem - i * PW;

    int ii = i - P;
    int jj = j - P;
    int rb = i - P - HH;
    int jr = j - P - HH;

    int f1 = 0, o1 = 0;

    if (f < 4) {
        // north faces: _pn
        int n   = f;
        int Ft  = (n + 1) & 3;
        int Ftl = (n + 2) & 3;
        int Fl  = (n + 3) & 3;
        int Fbl = (n + 3) & 3;
        int Fb  = n + 4;
        int Fbr = n + 8;
        int Fr  = 4 + ((n + 1) & 3);
        int Ftr = (n + 1) & 3;
        if (i < P) {
            if (j < P)            { f1 = Ftl; o1 = idx64(P-1-i, P-1-j); }
            else if (j < P + HH)  { f1 = Ft;  o1 = idx64(jj, P-1-i); }
            else                  { f1 = Ftr; o1 = idx64(HH-P+i, jr); }
        } else if (i < P + HH) {
            if (j < P)            { f1 = Fl;  o1 = idx64(P-1-j, ii); }
            else if (j < P + HH)  { f1 = n;   o1 = idx64(ii, jj); }
            else                  { f1 = Fr;  o1 = idx64(ii, jr); }
        } else {
            if (j < P)            { f1 = Fbl; o1 = idx64(rb, HH-P+j); }
            else if (j < P + HH)  { f1 = Fb;  o1 = idx64(rb, jj); }
            else                  { f1 = Fbr; o1 = idx64(rb, jr); }
        }
    } else if (f < 8) {
        // equator faces: _pe (blend diagonals store src1; pad blends inline)
        int k   = f - 4;
        int Ft  = k;
        int Fl  = (k + 3) & 3;
        int Fbl = 4 + ((k + 3) & 3);
        int Fb  = 8 + ((k + 3) & 3);
        int Fr  = 8 + k;
        int Ftr = 4 + ((k + 1) & 3);
        if (i < P) {
            if (j < P) {
                if (i == j)       { f1 = Ft; o1 = idx64(HH-P+i, 0); }
                else if (j > i)   { f1 = Ft; o1 = idx64(HH-P+i, j-i-1); }
                else              { f1 = Fl; o1 = idx64(i-j-1, HH-P+j); }
            }
            else if (j < P + HH)  { f1 = Ft;  o1 = idx64(HH-P+i, jj); }
            else                  { f1 = Ftr; o1 = idx64(HH-P+i, jr); }
        } else if (i < P + HH) {
            if (j < P)            { f1 = Fl;  o1 = idx64(ii, HH-P+j); }
            else if (j < P + HH)  { f1 = f;   o1 = idx64(ii, jj); }
            else                  { f1 = Fr;  o1 = idx64(ii, jr); }
        } else {
            if (j < P)            { f1 = Fbl; o1 = idx64(rb, HH-P+j); }
            else if (j < P + HH)  { f1 = Fb;  o1 = idx64(rb, jj); }
            else {
                if (rb == jr)     { f1 = Fb; o1 = idx64(rb, HH-1); }
                else if (jr < rb) { f1 = Fb; o1 = idx64(rb, HH-rb+jr); }
                else              { f1 = Fr; o1 = idx64(HH-jr+rb, jr); }
            }
        }
    } else {
        // south faces: _ps
        int m   = f - 8;
        int Ft  = 4 + ((m + 1) & 3);
        int Ftl = m;
        int Fl  = 4 + m;
        int Fbl = 8 + ((m + 3) & 3);
        int Fb  = 8 + ((m + 3) & 3);
        int Fbr = 8 + ((m + 2) & 3);
        int Fr  = 8 + ((m + 1) & 3);
        int Ftr = 8 + ((m + 1) & 3);
        if (i < P) {
            if (j < P)            { f1 = Ftl; o1 = idx64(HH-P+i, HH-P+j); }
            else if (j < P + HH)  { f1 = Ft;  o1 = idx64(HH-P+i, jj); }
            else                  { f1 = Ftr; o1 = idx64(HH-P+i, jr); }
        } else if (i < P + HH) {
            if (j < P)            { f1 = Fl;  o1 = idx64(ii, HH-P+j); }
            else if (j < P + HH)  { f1 = f;   o1 = idx64(ii, jj); }
            else                  { f1 = Fr;  o1 = idx64(HH-1-jr, ii); }
        } else {
            if (j < P)            { f1 = Fbl; o1 = idx64(rb, HH-P+j); }
            else if (j < P + HH)  { f1 = Fb;  o1 = idx64(jj, HH-1-rb); }
            else                  { f1 = Fbr; o1 = idx64(HH-1-rb, HH-1-jr); }
        }
    }

    g_tab16[t] = (unsigned short)((f1 << 12) | o1);
}

__global__ __launch_bounds__(256)
void pad_kernel(const float* __restrict__ in, float* __restrict__ out) {
    __shared__ float4 s4[HH * HH / 4];    // 16 KB: own face plane

    int rest = blockIdx.x;                // bf*NC + ch
    int ch   = rest & (NC - 1);
    int bf   = rest >> 8;
    int b    = bf / NFACE;
    int fo   = bf - b * NFACE;

    int sbase    = ((b * NFACE) << 20) | (ch << 12);
    const float* facep = in + sbase + (fo << 20);

    // Phase 1: stage own face, fully coalesced (issue first; drains async).
    {
        const float4* face4 = reinterpret_cast<const float4*>(facep);
        #pragma unroll
        for (int t = threadIdx.x; t < (HH * HH / 4); t += 256)
            s4[t] = __ldg(face4 + t);
    }

    float4* out4 = reinterpret_cast<float4*>(out) + (size_t)rest * NQPP;
    const unsigned short* tab = &g_tab16[fo * NPLANE];

    // Loop B: 196 irregular quads, global memory only (overlaps smem fill).
    // e < 34            -> q = e                 (border rows 0,1)
    // e < 68            -> q = 1122 + (e-34)     (border rows 66,67)
    // else e2 = e-68    -> center row r=e2>>1, side=e2&1 -> q=(r+2)*17 + (side?16:0)
    if (threadIdx.x < 196) {
        int e = threadIdx.x;
        float4 v;
        if (e < 68) {
            int q = (e < 34) ? e : (1122 + e - 34);
            ushort4 t4 = *reinterpret_cast<const ushort4*>(&tab[q * 4]);
            v.x = __ldg(in + sbase + ((t4.x >> 12) << 20) + (t4.x & 4095));
            v.y = __ldg(in + sbase + ((t4.y >> 12) << 20) + (t4.y & 4095));
            v.z = __ldg(in + sbase + ((t4.z >> 12) << 20) + (t4.z & 4095));
            v.w = __ldg(in + sbase + ((t4.w >> 12) << 20) + (t4.w & 4095));

            // blended _tl/_br diagonal positions: equator faces only
            if ((unsigned)(fo - 4) < 4) {
                int k = fo - 4;
                if (q == 0) {             // (0,0) -> x
                    v.x = 0.5f * (__ldg(in + sbase + (k << 20)             + idx64(HH-P, 0)) +
                                  __ldg(in + sbase + (((k+3)&3) << 20)     + idx64(0, HH-P)));
                } else if (q == 17) {     // (1,1) -> y
                    v.y = 0.5f * (__ldg(in + sbase + (k << 20)             + idx64(HH-1, 0)) +
                                  __ldg(in + sbase + (((k+3)&3) << 20)     + idx64(0, HH-1)));
                } else if (q == 1138) {   // (66,66) -> z
                    v.z = 0.5f * (__ldg(in + sbase + ((8+((k+3)&3)) << 20) + idx64(0, HH-1)) +
                                  __ldg(in + sbase + ((8+k) << 20)         + idx64(HH-1, 0)));
                } else if (q == 1155) {   // (67,67) -> w
                    v.w = 0.5f * (__ldg(in + sbase + ((8+((k+3)&3)) << 20) + idx64(1, HH-1)) +
                                  __ldg(in + sbase + ((8+k) << 20)         + idx64(HH-1, 1)));
                }
            }
            __stcs(out4 + q, v);
        } else {
            int e2   = e - 68;
            int r    = e2 >> 1;           // face row 0..63
            int side = e2 & 1;
            const float* grow = facep + r * HH;
            if (side == 0) {              // jq = 0: table x,y; own cols 0,1
                int q = (r + 2) * 17;
                ushort2 t2 = *reinterpret_cast<const ushort2*>(&tab[q * 4]);
                v.x = __ldg(in + sbase + ((t2.x >> 12) << 20) + (t2.x & 4095));
                v.y = __ldg(in + sbase + ((t2.y >> 12) << 20) + (t2.y & 4095));
                v.z = __ldg(grow + 0);
                v.w = __ldg(grow + 1);
                __stcs(out4 + q, v);
            } else {                      // jq = 16: own cols 62,63; table z,w
                int q = (r + 2) * 17 + 16;
                ushort2 t2 = *reinterpret_cast<const ushort2*>(&tab[q * 4 + 2]);
                v.x = __ldg(grow + 62);
                v.y = __ldg(grow + 63);
                v.z = __ldg(in + sbase + ((t2.x >> 12) << 20) + (t2.x & 4095));
                v.w = __ldg(in + sbase + ((t2.y >> 12) << 20) + (t2.y & 4095));
                __stcs(out4 + q, v);
            }
        }
    }

    __syncthreads();

    // Loop A: 960 interior quads, branch-free, convergent.
    // t -> face row r = t/15, jq = t%15 + 1, output q = (r+2)*17 + jq.
    #pragma unroll
    for (int t = threadIdx.x; t < 960; t += 256) {
        int r  = t / 15;
        int jq = t - r * 15 + 1;
        int base = r * 16;
        float4 A = s4[base + jq - 1];
        float4 B = s4[base + jq];
        float4 v = make_float4(A.z, A.w, B.x, B.y);
        __stcs(out4 + (r + 2) * 17 + jq, v);
    }
}

extern "C" void kernel_launch(void* const* d_in, const int* in_sizes, int n_in,
                              void* d_out, int out_size) {
    const float* in = (const float*)d_in[0];
    float* out = (float*)d_out;

    build_table_kernel<<<(NTAB + 255) / 256, 256>>>();

    int nplanes = out_size / NPLANE;           // 96*256 = 24576 blocks
    pad_kernel<<<nplanes, 256>>>(in, out);
}